// round 10
// baseline (speedup 1.0000x reference)
#include <cuda_runtime.h>
#include <math.h>

#define NKNOT 1024
#define NW    1020          // NUM_KNOTS - DEGREE - 1

// fp32 images of +/-pi (np.linspace endpoints after float32 cast)
#define T_LO (-3.14159274101257324218750f)
#define T_HI ( 3.14159274101257324218750f)

// 1023/(2*pi) split hi+lo (hi = correctly-rounded fp32, lo = residual)
#define INVH_HI 162.81578063964843750f
#define INVH_LO (-8.2343605185432045e-08f)
#define S_OFF   511.5f       // pi * 1023/(2*pi), exactly representable

#define THREADS 256
#define ELEMS   4

__global__ __launch_bounds__(THREADS) void bspline_act_kernel(
    const float* __restrict__ x,
    const float* __restrict__ w,
    float* __restrict__ out)
{
    // No shared memory, no barrier: the 4 KB weight table lives in L1 after the
    // first touches (L1 persists within a launch; hit latency ~39cyc ≈ LDS).
    const int base = (blockIdx.x * THREADS + threadIdx.x) * ELEMS;

    float4 xv = *reinterpret_cast<const float4*>(x + base);
    float xs[4] = {xv.x, xv.y, xv.z, xv.w};
    float r[4];

#pragma unroll
    for (int e = 0; e < 4; e++) {
        float xx = xs[e];

        // interval index
        float s1 = fmaf(xx, INVH_HI, S_OFF);
        int i = (int)s1;
        i = min(max(i, 0), NKNOT - 2);

        // compensated local coordinate: 511.5 - i exact; lo-term fixes INVH_HI's
        // representation error. u accurate to ~1e-7 vs ideal uniform grid.
        float offi = S_OFF - (float)i;
        float u = fmaf(xx, INVH_LO, fmaf(xx, INVH_HI, offi));

        // 4 weight taps w[i-3..i], clamped gather + select-zero at the edges.
        // All four loads are independent -> issued back-to-back (MLP=4).
        int c = i - 3;
        int c0 = max(c,     0);
        int c1 = max(c + 1, 0);
        int c2 = max(c + 2, 0);
        int c3 = min(i, NW - 1);
        float w0 = __ldg(w + c0);
        float w1 = __ldg(w + c1);
        float w2 = __ldg(w + c2);
        float w3 = __ldg(w + c3);
        w0 = (c     >= 0) ? w0 : 0.0f;
        w1 = (c + 1 >= 0) ? w1 : 0.0f;
        w2 = (c + 2 >= 0) ? w2 : 0.0f;
        w3 = (i < NW)     ? w3 : 0.0f;   // i in [0,1022]; only 1020..1022 clipped

        // uniform cubic B-spline blend
        const float SIXTH = 0.16666666666666666f;
        float omu = 1.0f - u;
        float u2  = u * u;
        float u3  = u2 * u;
        float N0 = omu * omu * omu * SIXTH;
        float N1 = fmaf(3.0f, u3, fmaf(-6.0f, u2, 4.0f)) * SIXTH;
        float N2 = fmaf(-3.0f, u3, fmaf(3.0f, u2, fmaf(3.0f, u, 1.0f))) * SIXTH;
        float N3 = u3 * SIXTH;

        float acc = fmaf(N0, w0, fmaf(N1, w1, fmaf(N2, w2, N3 * w3)));
        r[e] = (xx >= T_LO && xx < T_HI) ? acc : 0.0f;
    }

    *reinterpret_cast<float4*>(out + base) = make_float4(r[0], r[1], r[2], r[3]);
}

extern "C" void kernel_launch(void* const* d_in, const int* in_sizes, int n_in,
                              void* d_out, int out_size) {
    const float* x = (const float*)d_in[0];
    const float* w = (const float*)d_in[1];
    float* out = (float*)d_out;
    int n = in_sizes[0];                         // 262144
    int blocks = n / (THREADS * ELEMS);          // 256, exact cover
    bspline_act_kernel<<<blocks, THREADS>>>(x, w, out);
}